// round 1
// baseline (speedup 1.0000x reference)
#include <cuda_runtime.h>
#include <math.h>

#define BATCH 16384
#define TM 128
#define TN 128
#define TK 8

// ---------------- scratch (no allocations allowed) ----------------
__device__ float g_h1[BATCH * 1024];   // trunk layer 1 out
__device__ float g_h2[BATCH * 1024];   // trunk layer 2 out
__device__ float g_a1[BATCH * 512];    // head layer 1 out (compacted by combo)
__device__ float g_a2[BATCH * 256];    // head layer 2 out (compacted)
__device__ int   g_rowmap[BATCH];      // compacted position -> original row
__device__ int   g_cnt[4];
__device__ int   g_off[5];
__device__ int   g_cur[4];

// ---------------- combo partitioning ----------------
__global__ void reset_k() {
    int t = threadIdx.x;
    if (t < 4) { g_cnt[t] = 0; g_cur[t] = 0; }
}

__global__ void count_k(const int* __restrict__ flags) {
    int i = blockIdx.x * blockDim.x + threadIdx.x;
    if (i < BATCH) {
        int c = flags[2 * i] * 2 + flags[2 * i + 1];
        atomicAdd(&g_cnt[c], 1);
    }
}

__global__ void scan_k() {
    g_off[0] = 0;
    for (int c = 0; c < 4; c++) {
        g_off[c + 1] = g_off[c] + g_cnt[c];
        g_cur[c] = g_off[c];
    }
}

__global__ void fill_k(const int* __restrict__ flags) {
    int i = blockIdx.x * blockDim.x + threadIdx.x;
    if (i < BATCH) {
        int c = flags[2 * i] * 2 + flags[2 * i + 1];
        int pos = atomicAdd(&g_cur[c], 1);
        g_rowmap[pos] = i;
    }
}

// ---------------- tiled fp32 GEMM + bias + relu ----------------
// MODE: 0 = dense rows 0..BATCH, 1 = gather rows via g_rowmap over g_off[c]..g_off[c+1],
//       2 = compact rows direct over same range
// ASRC: 0 = external A arg, 1 = g_h1, 2 = g_h2, 3 = g_a1
// DST : 0 = g_h1, 1 = g_h2, 2 = g_a1, 3 = g_a2
template <int MODE, int ASRC, int DST>
__global__ __launch_bounds__(256)
void gemm_bias_relu(const float* __restrict__ Aext,
                    const float* __restrict__ W,
                    const float* __restrict__ Bias,
                    int K, int N, int ldA)
{
    __shared__ float As[TK][TM + 4];
    __shared__ float Bs[TK][TN];

    const float* A = (ASRC == 0) ? Aext
                   : (ASRC == 1) ? g_h1
                   : (ASRC == 2) ? g_h2
                   : g_a1;
    float* Out = (DST == 0) ? g_h1 : (DST == 1 ? g_h2 : (DST == 2 ? g_a1 : g_a2));

    const int tid = threadIdx.x;
    const int c = blockIdx.z;

    int mstart, mend;
    if (MODE == 0) { mstart = 0; mend = BATCH; }
    else           { mstart = g_off[c]; mend = g_off[c + 1]; }

    const int m0 = mstart + blockIdx.y * TM;
    if (m0 >= mend) return;
    const int n0 = blockIdx.x * TN;

    const float* Wc = W + (size_t)c * K * N;
    const float* bc = Bias + (size_t)c * N;

    // A tile loader: thread loads one float4 (row = tid>>1, k-group = (tid&1)*4)
    const int arow = tid >> 1;
    const int acol = (tid & 1) << 2;
    int apos = m0 + arow;
    if (apos > mend - 1) apos = mend - 1;   // clamp; masked at store
    const int grow = (MODE == 1) ? g_rowmap[apos] : apos;
    const float* Aptr = A + (size_t)grow * ldA + acol;

    // W tile loader: thread loads one float4 (k-row = tid>>5, n = (tid&31)*4)
    const int brow = tid >> 5;
    const int bcol = (tid & 31) << 2;
    const float* Wptr = Wc + (size_t)brow * N + n0 + bcol;

    const int rbase = (tid >> 4) << 3;   // 8 output rows per thread
    const int cbase = (tid & 15) << 3;   // 8 output cols per thread

    float acc[8][8] = {};

    for (int k0 = 0; k0 < K; k0 += TK) {
        float4 av = *(const float4*)(Aptr + k0);
        float4 bv = *(const float4*)(Wptr + (size_t)k0 * N);
        As[acol + 0][arow] = av.x;
        As[acol + 1][arow] = av.y;
        As[acol + 2][arow] = av.z;
        As[acol + 3][arow] = av.w;
        *(float4*)&Bs[brow][bcol] = bv;
        __syncthreads();

        #pragma unroll
        for (int k = 0; k < TK; k++) {
            float ar[8], br[8];
            #pragma unroll
            for (int i = 0; i < 8; i++) ar[i] = As[k][rbase + i];
            float4 b0 = *(const float4*)&Bs[k][cbase];
            float4 b1 = *(const float4*)&Bs[k][cbase + 4];
            br[0] = b0.x; br[1] = b0.y; br[2] = b0.z; br[3] = b0.w;
            br[4] = b1.x; br[5] = b1.y; br[6] = b1.z; br[7] = b1.w;
            #pragma unroll
            for (int i = 0; i < 8; i++)
                #pragma unroll
                for (int j = 0; j < 8; j++)
                    acc[i][j] = fmaf(ar[i], br[j], acc[i][j]);
        }
        __syncthreads();
    }

    #pragma unroll
    for (int i = 0; i < 8; i++) {
        int m = m0 + rbase + i;
        if (MODE != 0 && m >= mend) break;
        float* orow = Out + (size_t)m * N + n0 + cbase;
        #pragma unroll
        for (int j = 0; j < 8; j++) {
            float v = acc[i][j] + bc[n0 + cbase + j];
            orow[j] = fmaxf(v, 0.0f);
        }
    }
}

// ---------------- final head (dot 256 + bias + sigmoid + scatter) ----------------
__global__ void head3_k(const float* __restrict__ HW3,
                        const float* __restrict__ Hb3,
                        float* __restrict__ out)
{
    int gwarp = (blockIdx.x * blockDim.x + threadIdx.x) >> 5;
    int lane = threadIdx.x & 31;
    if (gwarp >= BATCH) return;

    int c;
    if (gwarp < g_off[1]) c = 0;
    else if (gwarp < g_off[2]) c = 1;
    else if (gwarp < g_off[3]) c = 2;
    else c = 3;

    const float* a = g_a2 + (size_t)gwarp * 256;
    const float* w = HW3 + (size_t)c * 256;

    float s = 0.0f;
    #pragma unroll
    for (int j = lane; j < 256; j += 32) s = fmaf(a[j], w[j], s);
    #pragma unroll
    for (int o = 16; o; o >>= 1) s += __shfl_xor_sync(0xFFFFFFFFu, s, o);

    if (lane == 0) {
        s += Hb3[c];
        out[g_rowmap[gwarp]] = 1.0f / (1.0f + expf(-s));
    }
}

// ---------------- launch ----------------
extern "C" void kernel_launch(void* const* d_in, const int* in_sizes, int n_in,
                              void* d_out, int out_size)
{
    const float* x     = (const float*)d_in[0];
    const int*   flags = (const int*)  d_in[1];
    const float* W1    = (const float*)d_in[2];
    const float* b1    = (const float*)d_in[3];
    const float* W2    = (const float*)d_in[4];
    const float* b2    = (const float*)d_in[5];
    const float* HW1   = (const float*)d_in[6];
    const float* Hb1   = (const float*)d_in[7];
    const float* HW2   = (const float*)d_in[8];
    const float* Hb2   = (const float*)d_in[9];
    const float* HW3   = (const float*)d_in[10];
    const float* Hb3   = (const float*)d_in[11];
    float* out = (float*)d_out;

    reset_k<<<1, 32>>>();
    count_k<<<BATCH / 256, 256>>>(flags);
    scan_k<<<1, 1>>>();
    fill_k<<<BATCH / 256, 256>>>(flags);

    // trunk layer 1: [16384,256] @ [256,1024] -> g_h1
    gemm_bias_relu<0, 0, 0><<<dim3(1024 / TN, BATCH / TM, 1), 256>>>(x, W1, b1, 256, 1024, 256);
    // trunk layer 2: [16384,1024] @ [1024,1024] -> g_h2
    gemm_bias_relu<0, 1, 1><<<dim3(1024 / TN, BATCH / TM, 1), 256>>>(nullptr, W2, b2, 1024, 1024, 1024);
    // head layer 1 (gathered, per-combo): [cnt_c,1024] @ HW1[c] -> g_a1 (compacted)
    gemm_bias_relu<1, 2, 2><<<dim3(512 / TN, BATCH / TM, 4), 256>>>(nullptr, HW1, Hb1, 1024, 512, 1024);
    // head layer 2 (compacted, per-combo): [cnt_c,512] @ HW2[c] -> g_a2
    gemm_bias_relu<2, 3, 3><<<dim3(256 / TN, BATCH / TM, 4), 256>>>(nullptr, HW2, Hb2, 512, 256, 512);

    // final dot + sigmoid + scatter
    head3_k<<<(BATCH * 32) / 256, 256>>>(HW3, Hb3, out);
}

// round 3
// speedup vs baseline: 1.7000x; 1.7000x over previous
#include <cuda_runtime.h>
#include <cuda_bf16.h>
#include <math.h>
#include <stdint.h>

#define BATCH 16384
#define KC 64                       // K elements per SMEM stage
#define STAGE_BYTES 65536
#define A_HI_OFF 0
#define A_LO_OFF 16384
#define B_HI_OFF 32768
#define B_LO_OFF 49152
#define GEMM_SMEM (2 * STAGE_BYTES)

// ---------------- scratch (no allocations allowed) ----------------
__device__ __nv_bfloat16 g_h1h[BATCH * 1024];
__device__ __nv_bfloat16 g_h1l[BATCH * 1024];
__device__ __nv_bfloat16 g_h2h[BATCH * 1024];
__device__ __nv_bfloat16 g_h2l[BATCH * 1024];
__device__ __nv_bfloat16 g_a1h[BATCH * 512];
__device__ __nv_bfloat16 g_a1l[BATCH * 512];
__device__ float g_a2[BATCH * 256];
__device__ int   g_rowmap[BATCH];
__device__ int   g_cnt[4];
__device__ int   g_off[5];
__device__ int   g_cur[4];

// ---------------- helpers (baseline PTX only: sm_80-class, no 'a' features) ----
__device__ __forceinline__ uint32_t smem_u32(const void* p) {
    uint32_t a;
    asm("{ .reg .u64 t; cvta.to.shared.u64 t, %1; cvt.u32.u64 %0, t; }" : "=r"(a) : "l"(p));
    return a;
}
#define LDSM_X4(r0, r1, r2, r3, addr) \
    asm volatile("ldmatrix.sync.aligned.m8n8.x4.shared.b16 {%0,%1,%2,%3}, [%4];" \
                 : "=r"(r0), "=r"(r1), "=r"(r2), "=r"(r3) : "r"(addr))

__device__ __forceinline__ void mma_bf16(float* d, const uint32_t* a, uint32_t b0, uint32_t b1) {
    asm volatile(
        "mma.sync.aligned.m16n8k16.row.col.f32.bf16.bf16.f32 "
        "{%0,%1,%2,%3}, {%4,%5,%6,%7}, {%8,%9}, {%0,%1,%2,%3};"
        : "+f"(d[0]), "+f"(d[1]), "+f"(d[2]), "+f"(d[3])
        : "r"(a[0]), "r"(a[1]), "r"(a[2]), "r"(a[3]), "r"(b0), "r"(b1));
}

__device__ __forceinline__ uint32_t pack2(__nv_bfloat16 a, __nv_bfloat16 b) {
    return ((uint32_t)__bfloat16_as_ushort(b) << 16) | (uint32_t)__bfloat16_as_ushort(a);
}
__device__ __forceinline__ void split4(float a, float b, float c, float d, uint2& h, uint2& l) {
    __nv_bfloat16 ha = __float2bfloat16(a), hb = __float2bfloat16(b);
    __nv_bfloat16 hc = __float2bfloat16(c), hd = __float2bfloat16(d);
    __nv_bfloat16 la = __float2bfloat16(a - __bfloat162float(ha));
    __nv_bfloat16 lb = __float2bfloat16(b - __bfloat162float(hb));
    __nv_bfloat16 lc = __float2bfloat16(c - __bfloat162float(hc));
    __nv_bfloat16 ld = __float2bfloat16(d - __bfloat162float(hd));
    h.x = pack2(ha, hb); h.y = pack2(hc, hd);
    l.x = pack2(la, lb); l.y = pack2(lc, ld);
}
__device__ __forceinline__ uint32_t swz(uint32_t off) { return off ^ ((off >> 3) & 0x70); }

// ---------------- combo partitioning ----------------
__global__ void reset_k() {
    int t = threadIdx.x;
    if (t < 4) { g_cnt[t] = 0; g_cur[t] = 0; }
}
__global__ void count_k(const int* __restrict__ flags) {
    int i = blockIdx.x * blockDim.x + threadIdx.x;
    if (i < BATCH) atomicAdd(&g_cnt[flags[2 * i] * 2 + flags[2 * i + 1]], 1);
}
__global__ void scan_k() {
    g_off[0] = 0;
    for (int c = 0; c < 4; c++) { g_off[c + 1] = g_off[c] + g_cnt[c]; g_cur[c] = g_off[c]; }
}
__global__ void fill_k(const int* __restrict__ flags) {
    int i = blockIdx.x * blockDim.x + threadIdx.x;
    if (i < BATCH) {
        int c = flags[2 * i] * 2 + flags[2 * i + 1];
        g_rowmap[atomicAdd(&g_cur[c], 1)] = i;
    }
}

// ---------------- warp-MMA bf16x3 GEMM + bias + relu ----------------
// MODE: 0 dense, 1 gather via g_rowmap, 2 compact
// ASRC: 0 ext fp32, 1 g_h1 pair, 2 g_h2 pair, 3 g_a1 pair
// DST : 0 g_h1 pair, 1 g_h2 pair, 2 g_a1 pair, 3 g_a2 fp32
template <int MODE, int ASRC, int DST, int K, int N>
__global__ __launch_bounds__(256, 1)
void gemm_mma(const float* __restrict__ Aext,
              const float* __restrict__ W,
              const float* __restrict__ Bias)
{
    extern __shared__ __align__(1024) char smem[];

    constexpr int NK = K / KC;
    const int tid = threadIdx.x;
    const int c = blockIdx.z;

    int mstart, mend;
    if (MODE == 0) { mstart = 0; mend = BATCH; }
    else           { mstart = g_off[c]; mend = g_off[c + 1]; }
    const int m0 = mstart + blockIdx.y * 128;
    if (m0 >= mend) return;
    const int n0 = blockIdx.x * 128;

    const float* Wc = W + (size_t)c * K * N;
    const float* bc = Bias + (size_t)c * N;
    const uint32_t smb = smem_u32(smem);

    // ---- A loader mapping: 2 threads per row, 32 cols each ----
    const int ar = tid >> 1;
    const int acb = (tid & 1) * 32;
    int apos = m0 + ar;
    if (apos > mend - 1) apos = mend - 1;
    const int grow = (MODE == 1) ? g_rowmap[apos] : apos;

    const float* Af = (ASRC == 0) ? (Aext + (size_t)grow * K + acb) : nullptr;
    const __nv_bfloat16* Ahp = nullptr; const __nv_bfloat16* Alp = nullptr;
    if (ASRC == 1) { Ahp = g_h1h; Alp = g_h1l; }
    else if (ASRC == 2) { Ahp = g_h2h; Alp = g_h2l; }
    else if (ASRC == 3) { Ahp = g_a1h; Alp = g_a1l; }
    if (ASRC != 0) { Ahp += (size_t)grow * K + acb; Alp += (size_t)grow * K + acb; }

    // ---- B loader mapping: 4x4 transpose blocks ----
    const int nb_ = (tid & 31);
    const int kb0 = (tid >> 5);

    float4 aF[8]; uint2 aH[8], aL[8];
    float4 bR[2][4];

    auto loadA = [&](int k0) {
        if (ASRC == 0) {
            #pragma unroll
            for (int j = 0; j < 8; j++) aF[j] = *(const float4*)(Af + k0 + 4 * j);
        } else {
            #pragma unroll
            for (int j = 0; j < 8; j++) {
                aH[j] = *(const uint2*)(Ahp + k0 + 4 * j);
                aL[j] = *(const uint2*)(Alp + k0 + 4 * j);
            }
        }
    };
    auto loadB = [&](int k0) {
        #pragma unroll
        for (int blk = 0; blk < 2; blk++) {
            const int kb = kb0 + blk * 8;
            const float* p = Wc + (size_t)(k0 + kb * 4) * N + n0 + nb_ * 4;
            #pragma unroll
            for (int kk = 0; kk < 4; kk++)
                bR[blk][kk] = *(const float4*)(p + (size_t)kk * N);
        }
    };
    auto stsAB = [&](int s) {
        char* st = smem + s * STAGE_BYTES;
        #pragma unroll
        for (int j = 0; j < 8; j++) {
            uint32_t sw = swz((uint32_t)ar * 128 + (acb + 4 * j) * 2);
            uint2 uh, ul;
            if (ASRC == 0) { float4 v = aF[j]; split4(v.x, v.y, v.z, v.w, uh, ul); }
            else { uh = aH[j]; ul = aL[j]; }
            *(uint2*)(st + A_HI_OFF + sw) = uh;
            *(uint2*)(st + A_LO_OFF + sw) = ul;
        }
        #pragma unroll
        for (int blk = 0; blk < 2; blk++) {
            const int kb = kb0 + blk * 8;
            #pragma unroll
            for (int j = 0; j < 4; j++) {
                float v0 = ((const float*)&bR[blk][0])[j];
                float v1 = ((const float*)&bR[blk][1])[j];
                float v2 = ((const float*)&bR[blk][2])[j];
                float v3 = ((const float*)&bR[blk][3])[j];
                uint2 uh, ul;
                split4(v0, v1, v2, v3, uh, ul);
                uint32_t sw = swz((uint32_t)(nb_ * 4 + j) * 128 + kb * 8);
                *(uint2*)(st + B_HI_OFF + sw) = uh;
                *(uint2*)(st + B_LO_OFF + sw) = ul;
            }
        }
    };

    // ---- warp MMA state ----
    const int wid = tid >> 5;
    const int lane = tid & 31;
    const int wm = (wid & 3) * 32;    // warp m offset within tile (4 warps)
    const int wn = (wid >> 2) * 64;   // warp n offset within tile (2 warps)

    float acc[2][8][4];
    #pragma unroll
    for (int i = 0; i < 2; i++)
        #pragma unroll
        for (int j = 0; j < 8; j++)
            #pragma unroll
            for (int q = 0; q < 4; q++) acc[i][j][q] = 0.0f;

    // ldmatrix per-lane source rows
    const int mat = lane >> 3, rin = lane & 7;
    const int a_row = ((mat & 1) << 3) + rin;       // row within 16 (A: mats 0,1 = m0-7,m8-15 @k0; 2,3 @k+8)
    const int a_kh  = (mat >> 1) << 3;              // k-half offset (halves)
    const int b_row = ((mat >> 1) << 3) + rin;      // row within 16 (B: mats 0,1 = n0-7 @k0,k8; 2,3 = n8-15)
    const int b_kh  = (mat & 1) << 3;

    auto consume = [&](int s) {
        const uint32_t aHi = smb + s * STAGE_BYTES + A_HI_OFF;
        const uint32_t aLo = smb + s * STAGE_BYTES + A_LO_OFF;
        const uint32_t bHi = smb + s * STAGE_BYTES + B_HI_OFF;
        const uint32_t bLo = smb + s * STAGE_BYTES + B_LO_OFF;
        #pragma unroll
        for (int k16 = 0; k16 < KC / 16; k16++) {
            const int kh = k16 * 16;
            uint32_t ah[2][4], al[2][4], bh[4][4], bl[4][4];
            #pragma unroll
            for (int mi = 0; mi < 2; mi++) {
                uint32_t sw = swz((uint32_t)(wm + mi * 16 + a_row) * 128 + (kh + a_kh) * 2);
                LDSM_X4(ah[mi][0], ah[mi][1], ah[mi][2], ah[mi][3], aHi + sw);
                LDSM_X4(al[mi][0], al[mi][1], al[mi][2], al[mi][3], aLo + sw);
            }
            #pragma unroll
            for (int nj = 0; nj < 4; nj++) {
                uint32_t sw = swz((uint32_t)(wn + nj * 16 + b_row) * 128 + (kh + b_kh) * 2);
                LDSM_X4(bh[nj][0], bh[nj][1], bh[nj][2], bh[nj][3], bHi + sw);
                LDSM_X4(bl[nj][0], bl[nj][1], bl[nj][2], bl[nj][3], bLo + sw);
            }
            #pragma unroll
            for (int mi = 0; mi < 2; mi++)
                #pragma unroll
                for (int nj = 0; nj < 4; nj++)
                    #pragma unroll
                    for (int nn = 0; nn < 2; nn++) {
                        float* d = acc[mi][nj * 2 + nn];
                        mma_bf16(d, ah[mi], bh[nj][nn * 2], bh[nj][nn * 2 + 1]);
                        mma_bf16(d, al[mi], bh[nj][nn * 2], bh[nj][nn * 2 + 1]);
                        mma_bf16(d, ah[mi], bl[nj][nn * 2], bl[nj][nn * 2 + 1]);
                    }
        }
    };

    // ---- main loop ----
    loadA(0); loadB(0);
    for (int kc = 0; kc < NK; kc++) {
        const int s = kc & 1;
        stsAB(s);
        __syncthreads();
        if (kc + 1 < NK) { loadA((kc + 1) * KC); loadB((kc + 1) * KC); }
        consume(s);
        __syncthreads();
    }

    // ---- epilogue ----
    __nv_bfloat16 *Oh = nullptr, *Ol = nullptr;
    if (DST == 0) { Oh = g_h1h; Ol = g_h1l; }
    else if (DST == 1) { Oh = g_h2h; Ol = g_h2l; }
    else if (DST == 2) { Oh = g_a1h; Ol = g_a1l; }

    const int qrow = lane >> 2;
    const int qcol = (lane & 3) * 2;
    #pragma unroll
    for (int mi = 0; mi < 2; mi++) {
        #pragma unroll
        for (int half = 0; half < 2; half++) {
            const int m = m0 + wm + mi * 16 + qrow + half * 8;
            if (MODE != 0 && m >= mend) continue;
            #pragma unroll
            for (int nj = 0; nj < 8; nj++) {
                const int col = n0 + wn + nj * 8 + qcol;
                float v0 = acc[mi][nj][half * 2 + 0] + __ldg(bc + col);
                float v1 = acc[mi][nj][half * 2 + 1] + __ldg(bc + col + 1);
                v0 = fmaxf(v0, 0.0f); v1 = fmaxf(v1, 0.0f);
                if (DST == 3) {
                    *(float2*)(g_a2 + (size_t)m * N + col) = make_float2(v0, v1);
                } else {
                    __nv_bfloat16 h0 = __float2bfloat16(v0), h1 = __float2bfloat16(v1);
                    __nv_bfloat16 l0 = __float2bfloat16(v0 - __bfloat162float(h0));
                    __nv_bfloat16 l1 = __float2bfloat16(v1 - __bfloat162float(h1));
                    size_t o = (size_t)m * N + col;
                    *(uint32_t*)(Oh + o) = pack2(h0, h1);
                    *(uint32_t*)(Ol + o) = pack2(l0, l1);
                }
            }
        }
    }
}

// ---------------- final head (dot 256 + bias + sigmoid + scatter) ----------------
__global__ void head3_k(const float* __restrict__ HW3,
                        const float* __restrict__ Hb3,
                        float* __restrict__ out)
{
    int gwarp = (blockIdx.x * blockDim.x + threadIdx.x) >> 5;
    int lane = threadIdx.x & 31;
    if (gwarp >= BATCH) return;

    int c;
    if (gwarp < g_off[1]) c = 0;
    else if (gwarp < g_off[2]) c = 1;
    else if (gwarp < g_off[3]) c = 2;
    else c = 3;

    const float* a = g_a2 + (size_t)gwarp * 256;
    const float* w = HW3 + (size_t)c * 256;

    float s = 0.0f;
    #pragma unroll
    for (int j = lane; j < 256; j += 32) s = fmaf(a[j], w[j], s);
    #pragma unroll
    for (int o = 16; o; o >>= 1) s += __shfl_xor_sync(0xFFFFFFFFu, s, o);

    if (lane == 0) {
        s += Hb3[c];
        out[g_rowmap[gwarp]] = 1.0f / (1.0f + expf(-s));
    }
}

// ---------------- launch ----------------
extern "C" void kernel_launch(void* const* d_in, const int* in_sizes, int n_in,
                              void* d_out, int out_size)
{
    const float* x     = (const float*)d_in[0];
    const int*   flags = (const int*)  d_in[1];
    const float* W1    = (const float*)d_in[2];
    const float* b1    = (const float*)d_in[3];
    const float* W2    = (const float*)d_in[4];
    const float* b2    = (const float*)d_in[5];
    const float* HW1   = (const float*)d_in[6];
    const float* Hb1   = (const float*)d_in[7];
    const float* HW2   = (const float*)d_in[8];
    const float* Hb2   = (const float*)d_in[9];
    const float* HW3   = (const float*)d_in[10];
    const float* Hb3   = (const float*)d_in[11];
    float* out = (float*)d_out;

    cudaFuncSetAttribute(gemm_mma<0, 0, 0, 256, 1024>,
                         cudaFuncAttributeMaxDynamicSharedMemorySize, GEMM_SMEM);
    cudaFuncSetAttribute(gemm_mma<0, 1, 1, 1024, 1024>,
                         cudaFuncAttributeMaxDynamicSharedMemorySize, GEMM_SMEM);
    cudaFuncSetAttribute(gemm_mma<1, 2, 2, 1024, 512>,
                         cudaFuncAttributeMaxDynamicSharedMemorySize, GEMM_SMEM);
    cudaFuncSetAttribute(gemm_mma<2, 3, 3, 512, 256>,
                         cudaFuncAttributeMaxDynamicSharedMemorySize, GEMM_SMEM);

    reset_k<<<1, 32>>>();
    count_k<<<BATCH / 256, 256>>>(flags);
    scan_k<<<1, 1>>>();
    fill_k<<<BATCH / 256, 256>>>(flags);

    // trunk L1: [16384,256] @ [256,1024] -> h1 pair
    gemm_mma<0, 0, 0, 256, 1024><<<dim3(8, 128, 1), 256, GEMM_SMEM>>>(x, W1, b1);
    // trunk L2: [16384,1024] @ [1024,1024] -> h2 pair
    gemm_mma<0, 1, 1, 1024, 1024><<<dim3(8, 128, 1), 256, GEMM_SMEM>>>(nullptr, W2, b2);
    // head L1 (gather per-combo): [cnt_c,1024] @ HW1[c][1024,512] -> a1 pair (compacted)
    gemm_mma<1, 2, 2, 1024, 512><<<dim3(4, 128, 4), 256, GEMM_SMEM>>>(nullptr, HW1, Hb1);
    // head L2 (compact per-combo): [cnt_c,512] @ HW2[c][512,256] -> a2 fp32
    gemm_mma<2, 3, 3, 512, 256><<<dim3(2, 128, 4), 256, GEMM_SMEM>>>(nullptr, HW2, Hb2);

    head3_k<<<(BATCH * 32) / 256, 256>>>(HW3, Hb3, out);
}

// round 5
// speedup vs baseline: 2.6080x; 1.5341x over previous
#include <cuda_runtime.h>
#include <cuda_bf16.h>
#include <math.h>
#include <stdint.h>

#define BATCH 16384
#define KC 64                       // K elements per SMEM stage
#define STAGE_BYTES 65536
#define A_HI_OFF 0
#define A_LO_OFF 16384
#define B_HI_OFF 32768
#define B_LO_OFF 49152
#define NSTAGE 3
#define GEMM_SMEM (NSTAGE * STAGE_BYTES)

// ---------------- scratch (no allocations allowed) ----------------
__device__ __nv_bfloat16 g_xh[BATCH * 256],  g_xl[BATCH * 256];
__device__ __nv_bfloat16 g_h1h[BATCH * 1024], g_h1l[BATCH * 1024];
__device__ __nv_bfloat16 g_h2h[BATCH * 1024], g_h2l[BATCH * 1024];
__device__ __nv_bfloat16 g_a1h[BATCH * 512],  g_a1l[BATCH * 512];
__device__ float g_a2[BATCH * 256];
// weights, split + transposed to K-major + pre-swizzled blocked tiles
__device__ __nv_bfloat16 g_w1h[256 * 1024],      g_w1l[256 * 1024];
__device__ __nv_bfloat16 g_w2h[1024 * 1024],     g_w2l[1024 * 1024];
__device__ __nv_bfloat16 g_hw1h[4 * 1024 * 512], g_hw1l[4 * 1024 * 512];
__device__ __nv_bfloat16 g_hw2h[4 * 512 * 256],  g_hw2l[4 * 512 * 256];
__device__ int g_rowmap[BATCH];
__device__ int g_cnt[4];
__device__ int g_off[5];
__device__ int g_cur[4];

// ---------------- helpers (baseline PTX only) ----------------
__device__ __forceinline__ uint32_t smem_u32(const void* p) {
    uint32_t a;
    asm("{ .reg .u64 t; cvta.to.shared.u64 t, %1; cvt.u32.u64 %0, t; }" : "=r"(a) : "l"(p));
    return a;
}
#define LDSM_X4(r0, r1, r2, r3, addr) \
    asm volatile("ldmatrix.sync.aligned.m8n8.x4.shared.b16 {%0,%1,%2,%3}, [%4];" \
                 : "=r"(r0), "=r"(r1), "=r"(r2), "=r"(r3) : "r"(addr))
#define CP16(dst, src) \
    asm volatile("cp.async.cg.shared.global [%0], [%1], 16;" :: "r"(dst), "l"(src) : "memory")
#define CP_COMMIT() asm volatile("cp.async.commit_group;" ::: "memory")
#define CP_WAIT1() asm volatile("cp.async.wait_group 1;" ::: "memory")
#define CP_WAIT0() asm volatile("cp.async.wait_group 0;" ::: "memory")

__device__ __forceinline__ void mma_bf16(float* d, const uint32_t* a, uint32_t b0, uint32_t b1) {
    asm volatile(
        "mma.sync.aligned.m16n8k16.row.col.f32.bf16.bf16.f32 "
        "{%0,%1,%2,%3}, {%4,%5,%6,%7}, {%8,%9}, {%0,%1,%2,%3};"
        : "+f"(d[0]), "+f"(d[1]), "+f"(d[2]), "+f"(d[3])
        : "r"(a[0]), "r"(a[1]), "r"(a[2]), "r"(a[3]), "r"(b0), "r"(b1));
}
__device__ __forceinline__ uint32_t pack2(__nv_bfloat16 a, __nv_bfloat16 b) {
    return ((uint32_t)__bfloat16_as_ushort(b) << 16) | (uint32_t)__bfloat16_as_ushort(a);
}
__device__ __forceinline__ uint32_t swz(uint32_t off) { return off ^ ((off >> 3) & 0x70); }

// ---------------- prep: split x (+ reset counters) ----------------
__global__ void splitX_k(const float* __restrict__ x) {
    int idx = blockIdx.x * blockDim.x + threadIdx.x;
    if (blockIdx.x == 0 && threadIdx.x < 4) g_cnt[threadIdx.x] = 0;
    if (idx >= BATCH * 256 / 4) return;
    float4 v = *(const float4*)(x + (size_t)idx * 4);
    __nv_bfloat16 h0 = __float2bfloat16(v.x), h1 = __float2bfloat16(v.y);
    __nv_bfloat16 h2 = __float2bfloat16(v.z), h3 = __float2bfloat16(v.w);
    __nv_bfloat16 l0 = __float2bfloat16(v.x - __bfloat162float(h0));
    __nv_bfloat16 l1 = __float2bfloat16(v.y - __bfloat162float(h1));
    __nv_bfloat16 l2 = __float2bfloat16(v.z - __bfloat162float(h2));
    __nv_bfloat16 l3 = __float2bfloat16(v.w - __bfloat162float(h3));
    *(uint2*)(g_xh + (size_t)idx * 4) = make_uint2(pack2(h0, h1), pack2(h2, h3));
    *(uint2*)(g_xl + (size_t)idx * 4) = make_uint2(pack2(l0, l1), pack2(l2, l3));
}

// ---------------- prep: split + transpose + swizzle all weights ----------------
// dst blocked layout: [c][nt=N/128][kt=K/64][8192 elems]  (tile: n-row 0..127 x k 0..63,
// element (rr,kk) at byte swz(rr*128 + kk*2) within the 16KB tile)
__global__ void splitW_k(const float* __restrict__ W1, const float* __restrict__ W2,
                         const float* __restrict__ HW1, const float* __restrict__ HW2) {
    int z = blockIdx.z;
    int K, N, C;
    const float* src;
    __nv_bfloat16 *dh, *dl;
    if (z == 0)      { K = 256;  N = 1024; C = 1; src = W1;  dh = g_w1h;  dl = g_w1l; }
    else if (z == 1) { K = 1024; N = 1024; C = 1; src = W2;  dh = g_w2h;  dl = g_w2l; }
    else if (z == 2) { K = 1024; N = 512;  C = 4; src = HW1; dh = g_hw1h; dl = g_hw1l; }
    else             { K = 512;  N = 256;  C = 4; src = HW2; dh = g_hw2h; dl = g_hw2l; }
    const int kg = K >> 3;
    int idx = blockIdx.x * blockDim.x + threadIdx.x;
    if (idx >= C * N * kg) return;
    const int n_ = idx % N;
    const int t  = idx / N;
    const int k8 = (t % kg) * 8;
    const int c  = t / kg;

    const float* s = src + ((size_t)c * K + k8) * N + n_;
    __nv_bfloat16 hb[8], lb[8];
    #pragma unroll
    for (int j = 0; j < 8; j++) {
        float v = s[(size_t)j * N];
        hb[j] = __float2bfloat16(v);
        lb[j] = __float2bfloat16(v - __bfloat162float(hb[j]));
    }
    const int nt = n_ >> 7, rr = n_ & 127, kt = k8 >> 6, kk = k8 & 63;
    const size_t base = (((size_t)c * (N >> 7) + nt) * (K >> 6) + kt) * 8192;
    const uint32_t sw = swz((uint32_t)rr * 128 + kk * 2);
    *(uint4*)((char*)(dh + base) + sw) = *(uint4*)hb;
    *(uint4*)((char*)(dl + base) + sw) = *(uint4*)lb;
}

// ---------------- combo partitioning ----------------
__global__ void count_k(const int* __restrict__ flags) {
    int i = blockIdx.x * blockDim.x + threadIdx.x;
    if (i < BATCH) atomicAdd(&g_cnt[flags[2 * i] * 2 + flags[2 * i + 1]], 1);
}
__global__ void scan_k() {
    g_off[0] = 0;
    for (int c = 0; c < 4; c++) { g_off[c + 1] = g_off[c] + g_cnt[c]; g_cur[c] = g_off[c]; }
}
__global__ void fill_k(const int* __restrict__ flags) {
    int i = blockIdx.x * blockDim.x + threadIdx.x;
    if (i < BATCH) {
        int c = flags[2 * i] * 2 + flags[2 * i + 1];
        g_rowmap[atomicAdd(&g_cur[c], 1)] = i;
    }
}

// ---------------- warp-MMA bf16x3 GEMM + bias + relu (cp.async 3-stage) -------
// MODE: 0 dense, 1 gather via g_rowmap, 2 compact
// ASRC: 0 g_x pair, 1 g_h1 pair, 2 g_h2 pair, 3 g_a1 pair
// WSRC: 0 w1, 1 w2, 2 hw1, 3 hw2
// DST : 0 g_h1 pair, 1 g_h2 pair, 2 g_a1 pair, 3 g_a2 fp32
template <int MODE, int ASRC, int WSRC, int DST, int K, int N>
__global__ __launch_bounds__(256, 1)
void gemm_mma(const float* __restrict__ Bias)
{
    extern __shared__ __align__(1024) char smem[];
    constexpr int NK = K / KC;
    const int tid = threadIdx.x;
    const int c = blockIdx.z;

    int mstart, mend;
    if (MODE == 0) { mstart = 0; mend = BATCH; }
    else           { mstart = g_off[c]; mend = g_off[c + 1]; }
    const int m0 = mstart + blockIdx.y * 128;
    if (m0 >= mend) return;
    const int n0 = blockIdx.x * 128;

    const float* bc = Bias + (size_t)c * N;
    const uint32_t smb = smem_u32(smem);

    // ---- source pointers ----
    const __nv_bfloat16 *Abh, *Abl;
    if (ASRC == 0)      { Abh = g_xh;  Abl = g_xl; }
    else if (ASRC == 1) { Abh = g_h1h; Abl = g_h1l; }
    else if (ASRC == 2) { Abh = g_h2h; Abl = g_h2l; }
    else                { Abh = g_a1h; Abl = g_a1l; }
    const __nv_bfloat16 *Wbh, *Wbl;
    if (WSRC == 0)      { Wbh = g_w1h;  Wbl = g_w1l; }
    else if (WSRC == 1) { Wbh = g_w2h;  Wbl = g_w2l; }
    else if (WSRC == 2) { Wbh = g_hw1h; Wbl = g_hw1l; }
    else                { Wbh = g_hw2h; Wbl = g_hw2l; }
    const size_t wtile0 = (((size_t)c * (N >> 7) + blockIdx.x) * (K >> 6)) * 8192;
    const __nv_bfloat16* Wth = Wbh + wtile0;
    const __nv_bfloat16* Wtl = Wbl + wtile0;

    // ---- A loader mapping: 2 threads per row, 64B (32 elems) each ----
    const int ar = tid >> 1;
    const int ahalf = tid & 1;
    int apos = m0 + ar;
    if (apos > mend - 1) apos = mend - 1;
    const int grow = (MODE == 1) ? g_rowmap[apos] : apos;
    const __nv_bfloat16* Arh = Abh + (size_t)grow * K + ahalf * 32;
    const __nv_bfloat16* Arl = Abl + (size_t)grow * K + ahalf * 32;
    const uint32_t a_sw_base = (uint32_t)ar * 128 + ahalf * 64;

    auto issue = [&](int kc) {
        const int s = kc % NSTAGE;
        const uint32_t stb = smb + s * STAGE_BYTES;
        const int k0 = kc * KC;
        #pragma unroll
        for (int j = 0; j < 4; j++) {
            uint32_t sw = swz(a_sw_base + j * 16);
            CP16(stb + A_HI_OFF + sw, Arh + k0 + j * 8);
            CP16(stb + A_LO_OFF + sw, Arl + k0 + j * 8);
        }
        const __nv_bfloat16* wh = Wth + (size_t)kc * 8192 + tid * 8;
        const __nv_bfloat16* wl = Wtl + (size_t)kc * 8192 + tid * 8;
        #pragma unroll
        for (int j = 0; j < 4; j++) {
            CP16(stb + B_HI_OFF + tid * 16 + j * 4096, wh + j * 2048);
            CP16(stb + B_LO_OFF + tid * 16 + j * 4096, wl + j * 2048);
        }
        CP_COMMIT();
    };

    // ---- warp MMA state ----
    const int wid = tid >> 5;
    const int lane = tid & 31;
    const int wm = (wid & 3) * 32;
    const int wn = (wid >> 2) * 64;

    float acc[2][8][4];
    #pragma unroll
    for (int i = 0; i < 2; i++)
        #pragma unroll
        for (int j = 0; j < 8; j++)
            #pragma unroll
            for (int q = 0; q < 4; q++) acc[i][j][q] = 0.0f;

    const int mat = lane >> 3, rin = lane & 7;
    const int a_row = ((mat & 1) << 3) + rin;
    const int a_kh  = (mat >> 1) << 3;
    const int b_row = ((mat >> 1) << 3) + rin;
    const int b_kh  = (mat & 1) << 3;

    auto consume = [&](int s) {
        const uint32_t aHi = smb + s * STAGE_BYTES + A_HI_OFF;
        const uint32_t aLo = smb + s * STAGE_BYTES + A_LO_OFF;
        const uint32_t bHi = smb + s * STAGE_BYTES + B_HI_OFF;
        const uint32_t bLo = smb + s * STAGE_BYTES + B_LO_OFF;
        #pragma unroll
        for (int k16 = 0; k16 < KC / 16; k16++) {
            const int kh = k16 * 16;
            uint32_t ah[2][4], al[2][4], bh[4][4], bl[4][4];
            #pragma unroll
            for (int mi = 0; mi < 2; mi++) {
                uint32_t sw = swz((uint32_t)(wm + mi * 16 + a_row) * 128 + (kh + a_kh) * 2);
                LDSM_X4(ah[mi][0], ah[mi][1], ah[mi][2], ah[mi][3], aHi + sw);
                LDSM_X4(al[mi][0], al[mi][1], al[mi][2], al[mi][3], aLo + sw);
            }
            #pragma unroll
            for (int nj = 0; nj < 4; nj++) {
                uint32_t sw = swz((uint32_t)(wn + nj * 16 + b_row) * 128 + (kh + b_kh) * 2);
                LDSM_X4(bh[nj][0], bh[nj][1], bh[nj][2], bh[nj][3], bHi + sw);
                LDSM_X4(bl[nj][0], bl[nj][1], bl[nj][2], bl[nj][3], bLo + sw);
            }
            #pragma unroll
            for (int mi = 0; mi < 2; mi++)
                #pragma unroll
                for (int nj = 0; nj < 4; nj++)
                    #pragma unroll
                    for (int nn = 0; nn < 2; nn++) {
                        float* d = acc[mi][nj * 2 + nn];
                        mma_bf16(d, ah[mi], bh[nj][nn * 2], bh[nj][nn * 2 + 1]);
                        mma_bf16(d, al[mi], bh[nj][nn * 2], bh[nj][nn * 2 + 1]);
                        mma_bf16(d, ah[mi], bl[nj][nn * 2], bl[nj][nn * 2 + 1]);
                    }
        }
    };

    // ---- 3-stage pipeline ----
    issue(0); issue(1);
    for (int kc = 0; kc < NK; kc++) {
        if (kc + 2 < NK) { CP_WAIT1(); } else { CP_WAIT0(); }
        __syncthreads();
        if (kc + 2 < NK) issue(kc + 2);
        consume(kc % NSTAGE);
    }

    // ---- epilogue ----
    __nv_bfloat16 *Oh = nullptr, *Ol = nullptr;
    if (DST == 0) { Oh = g_h1h; Ol = g_h1l; }
    else if (DST == 1) { Oh = g_h2h; Ol = g_h2l; }
    else if (DST == 2) { Oh = g_a1h; Ol = g_a1l; }

    const int qrow = lane >> 2;
    const int qcol = (lane & 3) * 2;
    #pragma unroll
    for (int mi = 0; mi < 2; mi++) {
        #pragma unroll
        for (int half = 0; half < 2; half++) {
            const int m = m0 + wm + mi * 16 + qrow + half * 8;
            if (MODE != 0 && m >= mend) continue;
            #pragma unroll
            for (int nj = 0; nj < 8; nj++) {
                const int col = n0 + wn + nj * 8 + qcol;
                float v0 = acc[mi][nj][half * 2 + 0] + __ldg(bc + col);
                float v1 = acc[mi][nj][half * 2 + 1] + __ldg(bc + col + 1);
                v0 = fmaxf(v0, 0.0f); v1 = fmaxf(v1, 0.0f);
                if (DST == 3) {
                    *(float2*)(g_a2 + (size_t)m * N + col) = make_float2(v0, v1);
                } else {
                    __nv_bfloat16 h0 = __float2bfloat16(v0), h1 = __float2bfloat16(v1);
                    __nv_bfloat16 l0 = __float2bfloat16(v0 - __bfloat162float(h0));
                    __nv_bfloat16 l1 = __float2bfloat16(v1 - __bfloat162float(h1));
                    size_t o = (size_t)m * N + col;
                    *(uint32_t*)(Oh + o) = pack2(h0, h1);
                    *(uint32_t*)(Ol + o) = pack2(l0, l1);
                }
            }
        }
    }
}

// ---------------- final head (dot 256 + bias + sigmoid + scatter) ----------------
__global__ void head3_k(const float* __restrict__ HW3,
                        const float* __restrict__ Hb3,
                        float* __restrict__ out)
{
    int gwarp = (blockIdx.x * blockDim.x + threadIdx.x) >> 5;
    int lane = threadIdx.x & 31;
    if (gwarp >= BATCH) return;

    int c;
    if (gwarp < g_off[1]) c = 0;
    else if (gwarp < g_off[2]) c = 1;
    else if (gwarp < g_off[3]) c = 2;
    else c = 3;

    const float* a = g_a2 + (size_t)gwarp * 256;
    const float* w = HW3 + (size_t)c * 256;

    float s = 0.0f;
    #pragma unroll
    for (int j = lane; j < 256; j += 32) s = fmaf(a[j], w[j], s);
    #pragma unroll
    for (int o = 16; o; o >>= 1) s += __shfl_xor_sync(0xFFFFFFFFu, s, o);

    if (lane == 0) {
        s += Hb3[c];
        out[g_rowmap[gwarp]] = 1.0f / (1.0f + expf(-s));
    }
}

// ---------------- launch ----------------
extern "C" void kernel_launch(void* const* d_in, const int* in_sizes, int n_in,
                              void* d_out, int out_size)
{
    const float* x     = (const float*)d_in[0];
    const int*   flags = (const int*)  d_in[1];
    const float* W1    = (const float*)d_in[2];
    const float* b1    = (const float*)d_in[3];
    const float* W2    = (const float*)d_in[4];
    const float* b2    = (const float*)d_in[5];
    const float* HW1   = (const float*)d_in[6];
    const float* Hb1   = (const float*)d_in[7];
    const float* HW2   = (const float*)d_in[8];
    const float* Hb2   = (const float*)d_in[9];
    const float* HW3   = (const float*)d_in[10];
    const float* Hb3   = (const float*)d_in[11];
    float* out = (float*)d_out;

    cudaFuncSetAttribute(gemm_mma<0, 0, 0, 0, 256, 1024>,
                         cudaFuncAttributeMaxDynamicSharedMemorySize, GEMM_SMEM);
    cudaFuncSetAttribute(gemm_mma<0, 1, 1, 1, 1024, 1024>,
                         cudaFuncAttributeMaxDynamicSharedMemorySize, GEMM_SMEM);
    cudaFuncSetAttribute(gemm_mma<1, 2, 2, 2, 1024, 512>,
                         cudaFuncAttributeMaxDynamicSharedMemorySize, GEMM_SMEM);
    cudaFuncSetAttribute(gemm_mma<2, 3, 3, 3, 512, 256>,
                         cudaFuncAttributeMaxDynamicSharedMemorySize, GEMM_SMEM);

    // prep (also resets combo counters)
    splitX_k<<<BATCH * 256 / 4 / 256, 256>>>(x);
    splitW_k<<<dim3(1024, 1, 4), 256>>>(W1, W2, HW1, HW2);
    // combo partitioning
    count_k<<<BATCH / 256, 256>>>(flags);
    scan_k<<<1, 1>>>();
    fill_k<<<BATCH / 256, 256>>>(flags);

    // trunk L1: [16384,256] @ [256,1024] -> h1 pair
    gemm_mma<0, 0, 0, 0, 256, 1024><<<dim3(8, 128, 1), 256, GEMM_SMEM>>>(b1);
    // trunk L2: [16384,1024] @ [1024,1024] -> h2 pair
    gemm_mma<0, 1, 1, 1, 1024, 1024><<<dim3(8, 128, 1), 256, GEMM_SMEM>>>(b2);
    // head L1 (gather per-combo): [cnt_c,1024] @ HW1[c][1024,512] -> a1 pair
    gemm_mma<1, 2, 2, 2, 1024, 512><<<dim3(4, 128, 4), 256, GEMM_SMEM>>>(Hb1);
    // head L2 (compact per-combo): [cnt_c,512] @ HW2[c][512,256] -> a2 fp32
    gemm_mma<2, 3, 3, 3, 512, 256><<<dim3(2, 128, 4), 256, GEMM_SMEM>>>(Hb2);

    head3_k<<<(BATCH * 32) / 256, 256>>>(HW3, Hb3, out);
}

// round 6
// speedup vs baseline: 2.6810x; 1.0280x over previous
#include <cuda_runtime.h>
#include <cuda_bf16.h>
#include <math.h>
#include <stdint.h>

#define BATCH 16384
#define KC 64                       // K elements per SMEM stage
#define STAGE_BYTES 65536
#define A_HI_OFF 0
#define A_LO_OFF 16384
#define B_HI_OFF 32768
#define B_LO_OFF 49152
#define NSTAGE 3
#define GEMM_SMEM (NSTAGE * STAGE_BYTES)
#define GTHREADS 512

// ---------------- scratch (no allocations allowed) ----------------
__device__ __nv_bfloat16 g_xh[BATCH * 256],  g_xl[BATCH * 256];
__device__ __nv_bfloat16 g_h1h[BATCH * 1024], g_h1l[BATCH * 1024];
__device__ __nv_bfloat16 g_h2h[BATCH * 1024], g_h2l[BATCH * 1024];
__device__ __nv_bfloat16 g_a1h[BATCH * 512],  g_a1l[BATCH * 512];
__device__ float g_a2[BATCH * 256];
// weights, split + transposed to K-major + pre-swizzled blocked tiles
__device__ __nv_bfloat16 g_w1h[256 * 1024],      g_w1l[256 * 1024];
__device__ __nv_bfloat16 g_w2h[1024 * 1024],     g_w2l[1024 * 1024];
__device__ __nv_bfloat16 g_hw1h[4 * 1024 * 512], g_hw1l[4 * 1024 * 512];
__device__ __nv_bfloat16 g_hw2h[4 * 512 * 256],  g_hw2l[4 * 512 * 256];
__device__ int g_rowmap[BATCH];
__device__ int g_off[5];

// ---------------- helpers (baseline PTX only) ----------------
__device__ __forceinline__ uint32_t smem_u32(const void* p) {
    uint32_t a;
    asm("{ .reg .u64 t; cvta.to.shared.u64 t, %1; cvt.u32.u64 %0, t; }" : "=r"(a) : "l"(p));
    return a;
}
#define LDSM_X4(r0, r1, r2, r3, addr) \
    asm volatile("ldmatrix.sync.aligned.m8n8.x4.shared.b16 {%0,%1,%2,%3}, [%4];" \
                 : "=r"(r0), "=r"(r1), "=r"(r2), "=r"(r3) : "r"(addr))
#define CP16(dst, src) \
    asm volatile("cp.async.cg.shared.global [%0], [%1], 16;" :: "r"(dst), "l"(src) : "memory")
#define CP_COMMIT() asm volatile("cp.async.commit_group;" ::: "memory")
#define CP_WAIT1() asm volatile("cp.async.wait_group 1;" ::: "memory")
#define CP_WAIT0() asm volatile("cp.async.wait_group 0;" ::: "memory")

__device__ __forceinline__ void mma_bf16(float* d, const uint32_t* a, uint32_t b0, uint32_t b1) {
    asm volatile(
        "mma.sync.aligned.m16n8k16.row.col.f32.bf16.bf16.f32 "
        "{%0,%1,%2,%3}, {%4,%5,%6,%7}, {%8,%9}, {%0,%1,%2,%3};"
        : "+f"(d[0]), "+f"(d[1]), "+f"(d[2]), "+f"(d[3])
        : "r"(a[0]), "r"(a[1]), "r"(a[2]), "r"(a[3]), "r"(b0), "r"(b1));
}
__device__ __forceinline__ uint32_t pack2(__nv_bfloat16 a, __nv_bfloat16 b) {
    return ((uint32_t)__bfloat16_as_ushort(b) << 16) | (uint32_t)__bfloat16_as_ushort(a);
}
__device__ __forceinline__ uint32_t swz(uint32_t off) { return off ^ ((off >> 3) & 0x70); }

// ---------------- prep: combo partitioning (one block, warp-aggregated) -------
__global__ void partition_k(const int* __restrict__ flags) {
    __shared__ int soff[4];
    const int tid = threadIdx.x;
    const int lane = tid & 31;

    if (tid < 4) soff[tid] = 0;
    __syncthreads();
    // count (warp-aggregated)
    for (int i = tid; i < BATCH; i += 1024) {
        int c = flags[2 * i] * 2 + flags[2 * i + 1];
        unsigned same = __match_any_sync(0xFFFFFFFFu, c);
        int leader = __ffs(same) - 1;
        if (lane == leader) atomicAdd(&soff[c], __popc(same));
    }
    __syncthreads();
    if (tid == 0) {
        int o = 0;
        #pragma unroll
        for (int c = 0; c < 4; c++) { int n = soff[c]; g_off[c] = o; soff[c] = o; o += n; }
        g_off[4] = o;
    }
    __syncthreads();
    // fill (warp-aggregated cursors)
    for (int i = tid; i < BATCH; i += 1024) {
        int c = flags[2 * i] * 2 + flags[2 * i + 1];
        unsigned same = __match_any_sync(0xFFFFFFFFu, c);
        int leader = __ffs(same) - 1;
        int rank = __popc(same & ((1u << lane) - 1u));
        int base = 0;
        if (lane == leader) base = atomicAdd(&soff[c], __popc(same));
        base = __shfl_sync(0xFFFFFFFFu, base, leader);
        g_rowmap[base + rank] = i;
    }
}

// ---------------- prep: split x ----------------
__global__ void splitX_k(const float* __restrict__ x) {
    int idx = blockIdx.x * blockDim.x + threadIdx.x;
    if (idx >= BATCH * 256 / 4) return;
    float4 v = *(const float4*)(x + (size_t)idx * 4);
    __nv_bfloat16 h0 = __float2bfloat16(v.x), h1 = __float2bfloat16(v.y);
    __nv_bfloat16 h2 = __float2bfloat16(v.z), h3 = __float2bfloat16(v.w);
    __nv_bfloat16 l0 = __float2bfloat16(v.x - __bfloat162float(h0));
    __nv_bfloat16 l1 = __float2bfloat16(v.y - __bfloat162float(h1));
    __nv_bfloat16 l2 = __float2bfloat16(v.z - __bfloat162float(h2));
    __nv_bfloat16 l3 = __float2bfloat16(v.w - __bfloat162float(h3));
    *(uint2*)(g_xh + (size_t)idx * 4) = make_uint2(pack2(h0, h1), pack2(h2, h3));
    *(uint2*)(g_xl + (size_t)idx * 4) = make_uint2(pack2(l0, l1), pack2(l2, l3));
}

// ---------------- prep: split + transpose + swizzle all weights ----------------
__global__ void splitW_k(const float* __restrict__ W1, const float* __restrict__ W2,
                         const float* __restrict__ HW1, const float* __restrict__ HW2) {
    int z = blockIdx.z;
    int K, N, C;
    const float* src;
    __nv_bfloat16 *dh, *dl;
    if (z == 0)      { K = 256;  N = 1024; C = 1; src = W1;  dh = g_w1h;  dl = g_w1l; }
    else if (z == 1) { K = 1024; N = 1024; C = 1; src = W2;  dh = g_w2h;  dl = g_w2l; }
    else if (z == 2) { K = 1024; N = 512;  C = 4; src = HW1; dh = g_hw1h; dl = g_hw1l; }
    else             { K = 512;  N = 256;  C = 4; src = HW2; dh = g_hw2h; dl = g_hw2l; }
    const int kg = K >> 3;
    int idx = blockIdx.x * blockDim.x + threadIdx.x;
    if (idx >= C * N * kg) return;
    const int n_ = idx % N;
    const int t  = idx / N;
    const int k8 = (t % kg) * 8;
    const int c  = t / kg;

    const float* s = src + ((size_t)c * K + k8) * N + n_;
    __nv_bfloat16 hb[8], lb[8];
    #pragma unroll
    for (int j = 0; j < 8; j++) {
        float v = s[(size_t)j * N];
        hb[j] = __float2bfloat16(v);
        lb[j] = __float2bfloat16(v - __bfloat162float(hb[j]));
    }
    const int nt = n_ >> 7, rr = n_ & 127, kt = k8 >> 6, kk = k8 & 63;
    const size_t base = (((size_t)c * (N >> 7) + nt) * (K >> 6) + kt) * 8192;
    const uint32_t sw = swz((uint32_t)rr * 128 + kk * 2);
    *(uint4*)((char*)(dh + base) + sw) = *(uint4*)hb;
    *(uint4*)((char*)(dl + base) + sw) = *(uint4*)lb;
}

// ---------------- warp-MMA bf16x3 GEMM + bias + relu (512 thr, 16 warps) ------
// MODE: 0 dense, 1 gather via g_rowmap, 2 compact
// ASRC: 0 g_x pair, 1 g_h1 pair, 2 g_h2 pair, 3 g_a1 pair
// WSRC: 0 w1, 1 w2, 2 hw1, 3 hw2
// DST : 0 g_h1 pair, 1 g_h2 pair, 2 g_a1 pair, 3 g_a2 fp32
template <int MODE, int ASRC, int WSRC, int DST, int K, int N>
__global__ __launch_bounds__(GTHREADS, 1)
void gemm_mma(const float* __restrict__ Bias)
{
    extern __shared__ __align__(1024) char smem[];
    constexpr int NK = K / KC;
    const int tid = threadIdx.x;
    const int c = blockIdx.z;

    int mstart, mend;
    if (MODE == 0) { mstart = 0; mend = BATCH; }
    else           { mstart = g_off[c]; mend = g_off[c + 1]; }
    const int m0 = mstart + blockIdx.y * 128;
    if (m0 >= mend) return;
    const int n0 = blockIdx.x * 128;

    const float* bc = Bias + (size_t)c * N;
    const uint32_t smb = smem_u32(smem);

    // ---- source pointers ----
    const __nv_bfloat16 *Abh, *Abl;
    if (ASRC == 0)      { Abh = g_xh;  Abl = g_xl; }
    else if (ASRC == 1) { Abh = g_h1h; Abl = g_h1l; }
    else if (ASRC == 2) { Abh = g_h2h; Abl = g_h2l; }
    else                { Abh = g_a1h; Abl = g_a1l; }
    const __nv_bfloat16 *Wbh, *Wbl;
    if (WSRC == 0)      { Wbh = g_w1h;  Wbl = g_w1l; }
    else if (WSRC == 1) { Wbh = g_w2h;  Wbl = g_w2l; }
    else if (WSRC == 2) { Wbh = g_hw1h; Wbl = g_hw1l; }
    else                { Wbh = g_hw2h; Wbl = g_hw2l; }
    const size_t wtile0 = (((size_t)c * (N >> 7) + blockIdx.x) * (K >> 6)) * 8192;
    const __nv_bfloat16* Wth = Wbh + wtile0;
    const __nv_bfloat16* Wtl = Wbl + wtile0;

    // ---- A loader mapping: 4 threads per row, 32B (16 elems) each ----
    const int ar = tid >> 2;          // 0..127
    const int aq = tid & 3;
    int apos = m0 + ar;
    if (apos > mend - 1) apos = mend - 1;
    const int grow = (MODE == 1) ? g_rowmap[apos] : apos;
    const __nv_bfloat16* Arh = Abh + (size_t)grow * K + aq * 16;
    const __nv_bfloat16* Arl = Abl + (size_t)grow * K + aq * 16;
    const uint32_t a_sw_base = (uint32_t)ar * 128 + aq * 32;

    auto issue = [&](int kc) {
        const int s = kc % NSTAGE;
        const uint32_t stb = smb + s * STAGE_BYTES;
        const int k0 = kc * KC;
        #pragma unroll
        for (int j = 0; j < 2; j++) {
            uint32_t sw = swz(a_sw_base + j * 16);
            CP16(stb + A_HI_OFF + sw, Arh + k0 + j * 8);
            CP16(stb + A_LO_OFF + sw, Arl + k0 + j * 8);
        }
        const __nv_bfloat16* wh = Wth + (size_t)kc * 8192 + tid * 16;
        const __nv_bfloat16* wl = Wtl + (size_t)kc * 8192 + tid * 16;
        #pragma unroll
        for (int j = 0; j < 2; j++) {
            CP16(stb + B_HI_OFF + tid * 32 + j * 16, wh + j * 8);
            CP16(stb + B_LO_OFF + tid * 32 + j * 16, wl + j * 8);
        }
        CP_COMMIT();
    };

    // ---- warp MMA state: 16 warps, warp tile 16x64 (8 m-slots x 2 n-slots) ----
    const int wid = tid >> 5;
    const int lane = tid & 31;
    const int wm = (wid & 7) * 16;
    const int wn = (wid >> 3) * 64;

    float acc[8][4];
    #pragma unroll
    for (int j = 0; j < 8; j++)
        #pragma unroll
        for (int q = 0; q < 4; q++) acc[j][q] = 0.0f;

    const int mat = lane >> 3, rin = lane & 7;
    const int a_row = ((mat & 1) << 3) + rin;
    const int a_kh  = (mat >> 1) << 3;
    const int b_row = ((mat >> 1) << 3) + rin;
    const int b_kh  = (mat & 1) << 3;

    auto consume = [&](int s) {
        const uint32_t aHi = smb + s * STAGE_BYTES + A_HI_OFF;
        const uint32_t aLo = smb + s * STAGE_BYTES + A_LO_OFF;
        const uint32_t bHi = smb + s * STAGE_BYTES + B_HI_OFF;
        const uint32_t bLo = smb + s * STAGE_BYTES + B_LO_OFF;
        #pragma unroll
        for (int k16 = 0; k16 < KC / 16; k16++) {
            const int kh = k16 * 16;
            uint32_t ah[4], al[4], bh[4][4], bl[4][4];
            {
                uint32_t sw = swz((uint32_t)(wm + a_row) * 128 + (kh + a_kh) * 2);
                LDSM_X4(ah[0], ah[1], ah[2], ah[3], aHi + sw);
                LDSM_X4(al[0], al[1], al[2], al[3], aLo + sw);
            }
            #pragma unroll
            for (int nj = 0; nj < 4; nj++) {
                uint32_t sw = swz((uint32_t)(wn + nj * 16 + b_row) * 128 + (kh + b_kh) * 2);
                LDSM_X4(bh[nj][0], bh[nj][1], bh[nj][2], bh[nj][3], bHi + sw);
                LDSM_X4(bl[nj][0], bl[nj][1], bl[nj][2], bl[nj][3], bLo + sw);
            }
            #pragma unroll
            for (int nj = 0; nj < 4; nj++)
                #pragma unroll
                for (int nn = 0; nn < 2; nn++) {
                    float* d = acc[nj * 2 + nn];
                    mma_bf16(d, ah, bh[nj][nn * 2], bh[nj][nn * 2 + 1]);
                    mma_bf16(d, al, bh[nj][nn * 2], bh[nj][nn * 2 + 1]);
                    mma_bf16(d, ah, bl[nj][nn * 2], bl[nj][nn * 2 + 1]);
                }
        }
    };

    // ---- 3-stage pipeline ----
    issue(0); issue(1);
    for (int kc = 0; kc < NK; kc++) {
        if (kc + 2 < NK) { CP_WAIT1(); } else { CP_WAIT0(); }
        __syncthreads();
        if (kc + 2 < NK) issue(kc + 2);
        consume(kc % NSTAGE);
    }

    // ---- epilogue ----
    __nv_bfloat16 *Oh = nullptr, *Ol = nullptr;
    if (DST == 0) { Oh = g_h1h; Ol = g_h1l; }
    else if (DST == 1) { Oh = g_h2h; Ol = g_h2l; }
    else if (DST == 2) { Oh = g_a1h; Ol = g_a1l; }

    const int qrow = lane >> 2;
    const int qcol = (lane & 3) * 2;
    #pragma unroll
    for (int half = 0; half < 2; half++) {
        const int m = m0 + wm + qrow + half * 8;
        if (MODE != 0 && m >= mend) continue;
        #pragma unroll
        for (int nj = 0; nj < 8; nj++) {
            const int col = n0 + wn + nj * 8 + qcol;
            float v0 = acc[nj][half * 2 + 0] + __ldg(bc + col);
            float v1 = acc[nj][half * 2 + 1] + __ldg(bc + col + 1);
            v0 = fmaxf(v0, 0.0f); v1 = fmaxf(v1, 0.0f);
            if (DST == 3) {
                *(float2*)(g_a2 + (size_t)m * N + col) = make_float2(v0, v1);
            } else {
                __nv_bfloat16 h0 = __float2bfloat16(v0), h1 = __float2bfloat16(v1);
                __nv_bfloat16 l0 = __float2bfloat16(v0 - __bfloat162float(h0));
                __nv_bfloat16 l1 = __float2bfloat16(v1 - __bfloat162float(h1));
                size_t o = (size_t)m * N + col;
                *(uint32_t*)(Oh + o) = pack2(h0, h1);
                *(uint32_t*)(Ol + o) = pack2(l0, l1);
            }
        }
    }
}

// ---------------- final head (dot 256 + bias + sigmoid + scatter) ----------------
__global__ void head3_k(const float* __restrict__ HW3,
                        const float* __restrict__ Hb3,
                        float* __restrict__ out)
{
    int gwarp = (blockIdx.x * blockDim.x + threadIdx.x) >> 5;
    int lane = threadIdx.x & 31;
    if (gwarp >= BATCH) return;

    int c;
    if (gwarp < g_off[1]) c = 0;
    else if (gwarp < g_off[2]) c = 1;
    else if (gwarp < g_off[3]) c = 2;
    else c = 3;

    const float* a = g_a2 + (size_t)gwarp * 256;
    const float* w = HW3 + (size_t)c * 256;

    float s = 0.0f;
    #pragma unroll
    for (int j = lane; j < 256; j += 32) s = fmaf(a[j], w[j], s);
    #pragma unroll
    for (int o = 16; o; o >>= 1) s += __shfl_xor_sync(0xFFFFFFFFu, s, o);

    if (lane == 0) {
        s += Hb3[c];
        out[g_rowmap[gwarp]] = 1.0f / (1.0f + expf(-s));
    }
}

// ---------------- launch ----------------
extern "C" void kernel_launch(void* const* d_in, const int* in_sizes, int n_in,
                              void* d_out, int out_size)
{
    const float* x     = (const float*)d_in[0];
    const int*   flags = (const int*)  d_in[1];
    const float* W1    = (const float*)d_in[2];
    const float* b1    = (const float*)d_in[3];
    const float* W2    = (const float*)d_in[4];
    const float* b2    = (const float*)d_in[5];
    const float* HW1   = (const float*)d_in[6];
    const float* Hb1   = (const float*)d_in[7];
    const float* HW2   = (const float*)d_in[8];
    const float* Hb2   = (const float*)d_in[9];
    const float* HW3   = (const float*)d_in[10];
    const float* Hb3   = (const float*)d_in[11];
    float* out = (float*)d_out;

    cudaFuncSetAttribute(gemm_mma<0, 0, 0, 0, 256, 1024>,
                         cudaFuncAttributeMaxDynamicSharedMemorySize, GEMM_SMEM);
    cudaFuncSetAttribute(gemm_mma<0, 1, 1, 1, 1024, 1024>,
                         cudaFuncAttributeMaxDynamicSharedMemorySize, GEMM_SMEM);
    cudaFuncSetAttribute(gemm_mma<1, 2, 2, 2, 1024, 512>,
                         cudaFuncAttributeMaxDynamicSharedMemorySize, GEMM_SMEM);
    cudaFuncSetAttribute(gemm_mma<2, 3, 3, 3, 512, 256>,
                         cudaFuncAttributeMaxDynamicSharedMemorySize, GEMM_SMEM);

    // prep
    partition_k<<<1, 1024>>>(flags);
    splitX_k<<<BATCH * 256 / 4 / 256, 256>>>(x);
    splitW_k<<<dim3(1024, 1, 4), 256>>>(W1, W2, HW1, HW2);

    // trunk L1: [16384,256] @ [256,1024] -> h1 pair
    gemm_mma<0, 0, 0, 0, 256, 1024><<<dim3(8, 128, 1), GTHREADS, GEMM_SMEM>>>(b1);
    // trunk L2: [16384,1024] @ [1024,1024] -> h2 pair
    gemm_mma<0, 1, 1, 1, 1024, 1024><<<dim3(8, 128, 1), GTHREADS, GEMM_SMEM>>>(b2);
    // head L1 (gather per-combo): [cnt_c,1024] @ HW1[c][1024,512] -> a1 pair
    gemm_mma<1, 2, 2, 2, 1024, 512><<<dim3(4, 128, 4), GTHREADS, GEMM_SMEM>>>(Hb1);
    // head L2 (compact per-combo): [cnt_c,512] @ HW2[c][512,256] -> a2 fp32
    gemm_mma<2, 3, 3, 3, 512, 256><<<dim3(2, 128, 4), GTHREADS, GEMM_SMEM>>>(Hb2);

    head3_k<<<(BATCH * 32) / 256, 256>>>(HW3, Hb3, out);
}